// round 1
// baseline (speedup 1.0000x reference)
#include <cuda_runtime.h>

// ConstrainNet residual:
//   out[0:64]            = V[0,:64] - x0
//   out[t*64 : t*64+64]  = [A B] @ V[t-1] - V[t,:64]   for t = 1..T-1
// Shapes: A (64,64), B (64,32), x0 (64), net_input = V (T=128, 96), out (T*64,)

constexpr int NS = 64;    // n_state
constexpr int NI = 32;    // n_input
constexpr int NA = 96;    // n_all
constexpr int T  = 128;

constexpr int BT      = 2;         // timesteps per block
constexpr int THREADS = BT * NS;   // 128
constexpr int PAD     = 65;        // smem row stride (floats), conflict-free

__global__ __launch_bounds__(THREADS, 1)
void constrainnet_kernel(const float* __restrict__ A,
                         const float* __restrict__ B,
                         const float* __restrict__ x0,
                         const float* __restrict__ V,
                         float* __restrict__ out) {
    // sAB[k*PAD + s] = AB[s][k]  (transposed so lanes read stride-1)
    __shared__ float sAB[NA * PAD];
    __shared__ float sV[(BT + 1) * NA];   // V rows t0-1 .. t0+BT-1

    const int tid = threadIdx.x;
    const int t0  = blockIdx.x * BT;

    // ---- stage A (64x64) via float4: 1024 vec loads ----
    {
        const float4* A4 = reinterpret_cast<const float4*>(A);
        #pragma unroll
        for (int i = tid; i < (NS * NS) / 4; i += THREADS) {
            float4 v = A4[i];
            int s  = i >> 4;          // row (i / 16)
            int k  = (i & 15) << 2;   // col base
            sAB[(k + 0) * PAD + s] = v.x;
            sAB[(k + 1) * PAD + s] = v.y;
            sAB[(k + 2) * PAD + s] = v.z;
            sAB[(k + 3) * PAD + s] = v.w;
        }
    }
    // ---- stage B (64x32) via float4: 512 vec loads ----
    {
        const float4* B4 = reinterpret_cast<const float4*>(B);
        #pragma unroll
        for (int i = tid; i < (NS * NI) / 4; i += THREADS) {
            float4 v = B4[i];
            int s  = i >> 3;          // row (i / 8)
            int k  = NS + ((i & 7) << 2);
            sAB[(k + 0) * PAD + s] = v.x;
            sAB[(k + 1) * PAD + s] = v.y;
            sAB[(k + 2) * PAD + s] = v.z;
            sAB[(k + 3) * PAD + s] = v.w;
        }
    }
    // ---- stage V rows t0-1 .. t0+BT-1 (BT+1 rows of 96) ----
    #pragma unroll
    for (int i = tid; i < (BT + 1) * NA; i += THREADS) {
        int r = t0 - 1 + i / NA;
        float v = 0.0f;
        if (r >= 0) v = V[r * NA + (i % NA)];
        sV[i] = v;
    }
    __syncthreads();

    const int g = tid >> 6;      // group: which timestep within block
    const int s = tid & 63;      // output element
    const int t = t0 + g;

    // sV row index for V[t-1] is g (since row 0 of sV holds t0-1)
    const float* vprev = &sV[g * NA];
    const float  vt_s  = sV[(g + 1) * NA + s];   // V[t][s]

    float r;
    if (t == 0) {
        r = vt_s - x0[s];
    } else {
        float acc = 0.0f;
        #pragma unroll
        for (int k = 0; k < NA; ++k)
            acc = fmaf(sAB[k * PAD + s], vprev[k], acc);
        r = acc - vt_s;
    }
    out[t * NS + s] = r;
}

extern "C" void kernel_launch(void* const* d_in, const int* in_sizes, int n_in,
                              void* d_out, int out_size) {
    const float* A  = (const float*)d_in[0];
    const float* B  = (const float*)d_in[1];
    const float* x0 = (const float*)d_in[2];
    const float* V  = (const float*)d_in[3];
    float* out = (float*)d_out;

    constrainnet_kernel<<<T / BT, THREADS>>>(A, B, x0, V, out);
}

// round 3
// speedup vs baseline: 1.0047x; 1.0047x over previous
#include <cuda_runtime.h>

// ConstrainNet residual:
//   out[0:64]            = V[0,:64] - x0
//   out[t*64 : t*64+64]  = [A B] @ V[t-1] - V[t,:64]   for t = 1..T-1
// Shapes: A (64,64), B (64,32), x0 (64), net_input = V (T=128, 96), out (T*64,)
//
// Layout: thread = (g, s, kh). g = timestep within block (BT=2),
// s = output row (64), kh = k-half (2-way split of the 96-wide dot product).
// Each thread keeps its 48-float AB row segment in registers (12 LDG.128),
// runs 48 FMAs into 4 accumulators, then shfl_xor(1) combines the two halves.
// No shared memory, no __syncthreads.

constexpr int NS = 64;
constexpr int NA = 96;
constexpr int T  = 128;
constexpr int BT = 2;
constexpr int THREADS = 256;   // 2 timesteps * 64 rows * 2 k-halves

__global__ __launch_bounds__(THREADS, 1)
void constrainnet_kernel(const float* __restrict__ A,
                         const float* __restrict__ B,
                         const float* __restrict__ x0,
                         const float* __restrict__ V,
                         float* __restrict__ out) {
    const int tid = threadIdx.x;
    const int g   = tid >> 7;        // timestep within block
    const int idx = tid & 127;
    const int s   = idx >> 1;        // output row
    const int kh  = idx & 1;         // k-half: [0,48) or [48,96)
    const int t   = blockIdx.x * BT + g;

    // AB row s, k-segment [kh*48, kh*48+48):
    //   kh=0: A[s][0:48]               -> X: A[s][0:16),  Y: A[s][16:48)
    //   kh=1: A[s][48:64] + B[s][0:32] -> X: A[s][48:64), Y: B[s][0:32)
    const float4* X4 = reinterpret_cast<const float4*>(A + s * 64 + kh * 48);
    const float4* Y4 = kh ? reinterpret_cast<const float4*>(B + s * 32)
                          : reinterpret_cast<const float4*>(A + s * 64 + 16);

    const int tprev = (t > 0) ? (t - 1) : 0;   // clamped; t==0 result overridden
    const float4* V4 = reinterpret_cast<const float4*>(V + tprev * NA + kh * 48);

    // Stage AB segment into registers (12 independent 128-bit loads).
    float4 ab[12];
    #pragma unroll
    for (int j = 0; j < 4; ++j) ab[j] = X4[j];
    #pragma unroll
    for (int j = 0; j < 8; ++j) ab[4 + j] = Y4[j];

    // 48 FMAs, 4 independent accumulator chains.
    float a0 = 0.f, a1 = 0.f, a2 = 0.f, a3 = 0.f;
    #pragma unroll
    for (int j = 0; j < 12; ++j) {
        float4 v = V4[j];
        a0 = fmaf(ab[j].x, v.x, a0);
        a1 = fmaf(ab[j].y, v.y, a1);
        a2 = fmaf(ab[j].z, v.z, a2);
        a3 = fmaf(ab[j].w, v.w, a3);
    }
    float dot = (a0 + a1) + (a2 + a3);
    dot += __shfl_xor_sync(0xFFFFFFFFu, dot, 1);   // combine the two k-halves

    const float vts = V[t * NA + s];
    float r = (t == 0) ? (vts - x0[s]) : (dot - vts);

    if (kh == 0) out[t * NS + s] = r;
}

extern "C" void kernel_launch(void* const* d_in, const int* in_sizes, int n_in,
                              void* d_out, int out_size) {
    const float* A  = (const float*)d_in[0];
    const float* B  = (const float*)d_in[1];
    const float* x0 = (const float*)d_in[2];
    const float* V  = (const float*)d_in[3];
    float* out = (float*)d_out;

    constrainnet_kernel<<<T / BT, THREADS>>>(A, B, x0, V, out);
}

// round 5
// speedup vs baseline: 1.0435x; 1.0386x over previous
#include <cuda_runtime.h>

// ConstrainNet residual:
//   out[0:64]            = V[0,:64] - x0
//   out[t*64 : t*64+64]  = [A B] @ V[t-1] - V[t,:64]   for t = 1..T-1
// Shapes: A (64,64), B (64,32), x0 (64), net_input = V (T=128, 96), out (T*64,)
//
// thread = (g, s, kh): g = timestep within block (BT=2), s = output row,
// kh = k-half of the 96-wide dot. 12 LDG.128 stage the AB row segment into
// registers, 48 FMAs into 4 accumulators, one shfl_xor(1) combines halves.
// No smem, no barriers. The final-subtract operand V[t][s] (and x0) is
// loaded FIRST since it sits on the result's dependence chain.

constexpr int NS = 64;
constexpr int NA = 96;
constexpr int T  = 128;
constexpr int BT = 2;
constexpr int THREADS = 256;

__global__ __launch_bounds__(THREADS, 1)
void constrainnet_kernel(const float* __restrict__ A,
                         const float* __restrict__ B,
                         const float* __restrict__ x0,
                         const float* __restrict__ V,
                         float* __restrict__ out) {
    const unsigned tid = threadIdx.x;
    const unsigned g   = tid >> 7;          // timestep within block
    const unsigned s   = (tid >> 1) & 63;   // output row
    const unsigned kh  = tid & 1;           // k-half
    const int t = (int)(blockIdx.x * BT + g);

    // Loads gating the final subtract: issue immediately.
    const float vts = __ldg(&V[t * NA + s]);
    const float x0s = (t == 0) ? __ldg(&x0[s]) : 0.0f;

    // AB row s, k-segment [kh*48, kh*48+48):
    //   kh=0: A[s][0:16) | A[s][16:48)
    //   kh=1: A[s][48:64) | B[s][0:32)
    const float4* X4 = reinterpret_cast<const float4*>(A + s * 64 + kh * 48);
    const float4* Y4 = kh ? reinterpret_cast<const float4*>(B + s * 32)
                          : reinterpret_cast<const float4*>(A + s * 64 + 16);

    const int tprev = (t > 0) ? (t - 1) : 0;   // clamped; t==0 overridden
    const float4* V4 = reinterpret_cast<const float4*>(V + tprev * NA + kh * 48);

    float4 ab[12];
    #pragma unroll
    for (int j = 0; j < 4; ++j) ab[j] = X4[j];
    #pragma unroll
    for (int j = 0; j < 8; ++j) ab[4 + j] = Y4[j];

    float a0 = 0.f, a1 = 0.f, a2 = 0.f, a3 = 0.f;
    #pragma unroll
    for (int j = 0; j < 12; ++j) {
        float4 v = V4[j];
        a0 = fmaf(ab[j].x, v.x, a0);
        a1 = fmaf(ab[j].y, v.y, a1);
        a2 = fmaf(ab[j].z, v.z, a2);
        a3 = fmaf(ab[j].w, v.w, a3);
    }
    float dot = (a0 + a1) + (a2 + a3);
    dot += __shfl_xor_sync(0xFFFFFFFFu, dot, 1);

    float r = (t == 0) ? (vts - x0s) : (dot - vts);

    if (kh == 0) out[t * NS + s] = r;
}

extern "C" void kernel_launch(void* const* d_in, const int* in_sizes, int n_in,
                              void* d_out, int out_size) {
    const float* A  = (const float*)d_in[0];
    const float* B  = (const float*)d_in[1];
    const float* x0 = (const float*)d_in[2];
    const float* V  = (const float*)d_in[3];
    float* out = (float*)d_out;

    constrainnet_kernel<<<T / BT, THREADS>>>(A, B, x0, V, out);
}